// round 8
// baseline (speedup 1.0000x reference)
#include <cuda_runtime.h>
#include <stdint.h>

// EmbeddingDropout: out[r, :] = weight[x[r], :] * mask[x[r]]
// x: [16384] int32, weight: [50257, 512] f32, mask: [50257] f32.
//
// R8: R3 structure (best: one warp per row, 4x512B coalesced quanta,
// streaming .cs stores) but weight reads issued as two plain 256-bit
// ld.global.nc.v8.f32 per thread (NO L2 policy — R7 showed the
// evict_last form is a slow path). Controlled A/B: v8 vs policy.

#define D 512
#define THREADS 256           // 8 warps -> 8 rows per block
#define ROWS_PER_BLOCK (THREADS / 32)

struct f32x8 { float v[8]; };

__device__ __forceinline__ f32x8 ldg256_nc(const void* p) {
    f32x8 r;
    asm volatile(
        "ld.global.nc.v8.f32 {%0,%1,%2,%3,%4,%5,%6,%7}, [%8];"
        : "=f"(r.v[0]), "=f"(r.v[1]), "=f"(r.v[2]), "=f"(r.v[3]),
          "=f"(r.v[4]), "=f"(r.v[5]), "=f"(r.v[6]), "=f"(r.v[7])
        : "l"(p));
    return r;
}

__device__ __forceinline__ void stg_cs_v4(void* p, float a, float b, float c, float d) {
    asm volatile("st.global.cs.v4.f32 [%0], {%1,%2,%3,%4};"
                 :: "l"(p), "f"(a), "f"(b), "f"(c), "f"(d)
                 : "memory");
}

__global__ __launch_bounds__(THREADS) void embedding_dropout_kernel(
    const int* __restrict__ x,            // [N]
    const float* __restrict__ weight,     // [V, D]
    const float* __restrict__ mask,       // [V]
    float* __restrict__ out,              // [N, D]
    int n_rows)
{
    int row  = (blockIdx.x * THREADS + threadIdx.x) >> 5;  // one warp per row
    int lane = threadIdx.x & 31;
    if (row >= n_rows) return;

    int idx = __ldg(&x[row]);             // broadcast across the warp
    float s = __ldg(&mask[idx]);

    const float* wrow = weight + (size_t)idx * D + lane * 8;
    float*       orow = out    + (size_t)row * D + lane * 8;

    // Two independent 32B loads per thread: 2 * 32 lanes * 8 f32 = 512 floats.
    f32x8 a = ldg256_nc(wrow);
    f32x8 b = ldg256_nc(wrow + 32 * 8);

    #pragma unroll
    for (int i = 0; i < 8; i++) { a.v[i] *= s; b.v[i] *= s; }

    stg_cs_v4(orow,              a.v[0], a.v[1], a.v[2], a.v[3]);
    stg_cs_v4(orow + 4,          a.v[4], a.v[5], a.v[6], a.v[7]);
    stg_cs_v4(orow + 32 * 8,     b.v[0], b.v[1], b.v[2], b.v[3]);
    stg_cs_v4(orow + 32 * 8 + 4, b.v[4], b.v[5], b.v[6], b.v[7]);
}

extern "C" void kernel_launch(void* const* d_in, const int* in_sizes, int n_in,
                              void* d_out, int out_size)
{
    // Identify inputs by element count: x=16384, weight=25731584, mask=50257.
    long long max_sz = -1, mid_sz = -1;
    int wi = -1, mi = -1, xi = -1;
    for (int i = 0; i < n_in; i++)
        if (in_sizes[i] > max_sz) { max_sz = in_sizes[i]; wi = i; }
    for (int i = 0; i < n_in; i++)
        if (i != wi && in_sizes[i] > mid_sz) { mid_sz = in_sizes[i]; mi = i; }
    for (int i = 0; i < n_in; i++)
        if (i != wi && i != mi) { xi = i; break; }

    const int*   x    = (const int*)d_in[xi];
    const float* w    = (const float*)d_in[wi];
    const float* mask = (const float*)d_in[mi];
    float*       out  = (float*)d_out;
    int n_rows = in_sizes[xi];

    int blocks = (n_rows + ROWS_PER_BLOCK - 1) / ROWS_PER_BLOCK;
    embedding_dropout_kernel<<<blocks, THREADS>>>(x, w, mask, out, n_rows);
}

// round 9
// speedup vs baseline: 1.4060x; 1.4060x over previous
#include <cuda_runtime.h>
#include <stdint.h>

// EmbeddingDropout: out[r, :] = weight[x[r], :] * mask[x[r]]
// x: [16384] int32 token ids, weight: [50257, 512] f32, mask: [50257] f32.
// Output: [16384, 512] f32.
//
// FINAL (= R3, best of 7 structural experiments at 10.69 us):
//   - one warp per row; each thread moves 4 independent float4 (LDG.128),
//     fully coalesced 512B quanta per warp-step
//   - __ldg on weight/mask (read-only path, dup-token L2 reuse)
//   - __stcs streaming stores: write-once 32 MB output marked evict-first
// Measured invariances: timed duration is flat (10.69-10.75 us) across
// MLP 1/4/8 per warp and store mechanisms; v8 loads and TMA bulk stores
// both regress. Kernel sits at the mixed-stream memory floor
// (~61 MB mandatory traffic) plus fixed replay overhead.

#define D 512
#define D4 (D / 4)            // 128 float4 per row
#define THREADS 256           // 8 warps -> 8 rows per block
#define ROWS_PER_BLOCK (THREADS / 32)

__global__ __launch_bounds__(THREADS) void embedding_dropout_kernel(
    const int* __restrict__ x,           // [N]
    const float4* __restrict__ weight,   // [V, D4]
    const float* __restrict__ mask,      // [V]
    float4* __restrict__ out,            // [N, D4]
    int n_rows)
{
    int row  = (blockIdx.x * THREADS + threadIdx.x) >> 5;  // one warp per row
    int lane = threadIdx.x & 31;
    if (row >= n_rows) return;

    int idx = __ldg(&x[row]);            // L1 broadcast across the warp
    float s = __ldg(&mask[idx]);

    const float4* wrow = weight + (size_t)idx * D4;
    float4*       orow = out    + (size_t)row * D4;

    float4 v[4];
    #pragma unroll
    for (int i = 0; i < 4; i++)          // 4 independent 512B-coalesced loads
        v[i] = __ldg(&wrow[lane + 32 * i]);

    #pragma unroll
    for (int i = 0; i < 4; i++) {
        v[i].x *= s; v[i].y *= s; v[i].z *= s; v[i].w *= s;
        __stcs(&orow[lane + 32 * i], v[i]);   // streaming: evict-first in L2
    }
}

extern "C" void kernel_launch(void* const* d_in, const int* in_sizes, int n_in,
                              void* d_out, int out_size)
{
    // Identify inputs by element count: x=16384, weight=25731584, mask=50257.
    long long max_sz = -1, mid_sz = -1;
    int wi = -1, mi = -1, xi = -1;
    for (int i = 0; i < n_in; i++)
        if (in_sizes[i] > max_sz) { max_sz = in_sizes[i]; wi = i; }
    for (int i = 0; i < n_in; i++)
        if (i != wi && in_sizes[i] > mid_sz) { mid_sz = in_sizes[i]; mi = i; }
    for (int i = 0; i < n_in; i++)
        if (i != wi && i != mi) { xi = i; break; }

    const int*    x    = (const int*)d_in[xi];
    const float4* w    = (const float4*)d_in[wi];
    const float*  mask = (const float*)d_in[mi];
    float4*       out  = (float4*)d_out;
    int n_rows = in_sizes[xi];

    int blocks = (n_rows + ROWS_PER_BLOCK - 1) / ROWS_PER_BLOCK;
    embedding_dropout_kernel<<<blocks, THREADS>>>(x, w, mask, out, n_rows);
}